// round 11
// baseline (speedup 1.0000x reference)
#include <cuda_runtime.h>
#include <cuda_bf16.h>

// ManifoldConstrainedHyperConnection — fused, G=4, 1024 threads (occ 50%),
// float2 d-slices, decoupled producer/consumer ring (no full-CTA barrier
// convoys): warps 0-1 double as router warps (reduce + softmax + sinkhorn)
// between their FULL sync and DONE arrive; workers stream A/B/F phases of
// consecutive groups back-to-back.
//
// Ring protocol (slot s = it&1):
//   workers (w2-31): A(g) B(g)->sP[s]  arrive FULL(s)  prefetch(g+1)
//                    sync DONE(s^1)    F(g-1) from sM[s^1]
//   routers (w0-1):  A(g) B(g)->sP[s]  sync FULL(s)  reduce sP[s]->sRaw[s]
//                    bar5(64)  sinkhorn -> sM[s]  bar6(64)  arrive DONE(s)
//                    prefetch(g+1)     F(g-1)
// Slot reuse is ordered by the FULL/DONE chain (see round analysis).

#define WRK 24
#define DDIM 2048
#define WS 4
#define THREADS 1024
#define NW 32
#define G 4
#define EPSV 1e-6f

#define SMEM_WR (WRK * DDIM)            // 49152 floats (192 KB)
#define SP_STRIDE 100
#define SP_SLOT (NW * SP_STRIDE)        // 3200 floats
#define OFF_SP   SMEM_WR
#define OFF_RAW  (OFF_SP + 2 * SP_SLOT)
#define OFF_M    (OFF_RAW + 2 * 96)
#define SMEM_FLOATS (OFF_M + 2 * 64)
#define SMEM_BYTES (SMEM_FLOATS * 4)    // ~218 KB

#define FULLM 0xffffffffu

// named barriers: FULL_s = 1+s, DONE_s = 3+s (count 1024); router-internal 5,6 (count 64)
#define BAR_ARRIVE(id)   asm volatile("bar.arrive %0, %1;" :: "r"(id), "r"(THREADS) : "memory")
#define BAR_SYNC_CTA(id) asm volatile("bar.sync %0, %1;"   :: "r"(id), "r"(THREADS) : "memory")
#define BAR_SYNC_R(id)   asm volatile("bar.sync %0, %1;"   :: "r"(id), "r"(64) : "memory")

__device__ __forceinline__ float2 ld_cg2(const float* p) {
    return __ldcg(reinterpret_cast<const float2*>(p));
}

#define BFLY_STEP(r, n, o)                                              \
    {                                                                   \
        const bool hi_ = (lane & (o)) != 0;                             \
        _Pragma("unroll")                                               \
        for (int v_ = 0; v_ < (n) / 2; v_++) {                          \
            float mine_  = hi_ ? r[v_ + (n) / 2] : r[v_];               \
            float other_ = hi_ ? r[v_] : r[v_ + (n) / 2];               \
            r[v_] = mine_ + __shfl_xor_sync(FULLM, other_, (o));        \
        }                                                               \
    }

__device__ __forceinline__ void mix_store(const float* __restrict__ x,
                                          float* __restrict__ out,
                                          const float* sMp, int g, int d0, int ntok)
{
    const int n0 = g * G;
    #pragma unroll
    for (int t = 0; t < G; t++) {
        if (n0 + t < ntok) {
            const float* p = x + (size_t)(n0 + t) * (WS * DDIM) + d0;
            float*       o = out + (size_t)(n0 + t) * (WS * DDIM) + d0;
            float2 x0 = ld_cg2(p);
            float2 x1 = ld_cg2(p + DDIM);
            float2 x2 = ld_cg2(p + 2 * DDIM);
            float2 x3 = ld_cg2(p + 3 * DDIM);
            #pragma unroll
            for (int i = 0; i < WS; i++) {
                float4 Mi = *reinterpret_cast<const float4*>(sMp + t * 16 + i * 4);
                float2 ov;
                ov.x = Mi.x*x0.x + Mi.y*x1.x + Mi.z*x2.x + Mi.w*x3.x;
                ov.y = Mi.x*x0.y + Mi.y*x1.y + Mi.z*x2.y + Mi.w*x3.y;
                __stcs(reinterpret_cast<float2*>(o + i * DDIM), ov);
            }
        }
    }
}

__global__ void __launch_bounds__(THREADS, 1)
mchc_kernel(const float* __restrict__ x, const float* __restrict__ Wr,
            const float* __restrict__ br, float* __restrict__ out, int ntok)
{
    extern __shared__ float sm[];
    float* sWr = sm;

    const int tid  = threadIdx.x;
    const int lane = tid & 31;
    const int warp = tid >> 5;
    const int d0   = tid * 2;

    for (int i = tid * 4; i < SMEM_WR; i += THREADS * 4)
        *reinterpret_cast<float4*>(sWr + i) = *reinterpret_cast<const float4*>(Wr + i);
    __syncthreads();

    const int ngroups = (ntok + G - 1) / G;
    const int gstride = gridDim.x;

    int it = 0;
    int gprev = -1;

    for (int g = blockIdx.x; g < ngroups; g += gstride, it++) {
        const int s  = it & 1;
        const int n0 = g * G;
        float* sP = sm + OFF_SP + s * SP_SLOT;

        // ---- A: pass-1 read (L2-warm) -> stream means ----
        float2 mx[G];
        #pragma unroll
        for (int t = 0; t < G; t++) {
            mx[t] = make_float2(0.f, 0.f);
            if (n0 + t < ntok) {
                const float* p = x + (size_t)(n0 + t) * (WS * DDIM) + d0;
                #pragma unroll
                for (int w = 0; w < WS; w++) {
                    float2 v = ld_cg2(p + w * DDIM);
                    mx[t].x += v.x; mx[t].y += v.y;
                }
                mx[t].x *= 0.25f; mx[t].y *= 0.25f;
            }
        }

        // ---- B: router partials, 3 sets of 32 values (v = 4k + t) ----
        float res0, res1, res2;
        #pragma unroll
        for (int set = 0; set < 3; set++) {
            float a[32];
            #pragma unroll
            for (int kk = 0; kk < 8; kk++) {
                const int k = 8 * set + kk;
                float2 wv = *reinterpret_cast<const float2*>(sWr + k * DDIM + d0);
                #pragma unroll
                for (int t = 0; t < G; t++)
                    a[kk * 4 + t] = wv.x * mx[t].x + wv.y * mx[t].y;
            }
            BFLY_STEP(a, 32, 16)
            BFLY_STEP(a, 16, 8)
            BFLY_STEP(a, 8, 4)
            BFLY_STEP(a, 4, 2)
            BFLY_STEP(a, 2, 1)
            if (set == 0) res0 = a[0];
            else if (set == 1) res1 = a[0];
            else res2 = a[0];
        }
        sP[warp * SP_STRIDE + lane]      = res0;
        sP[warp * SP_STRIDE + 32 + lane] = res1;
        sP[warp * SP_STRIDE + 64 + lane] = res2;

        if (warp >= 2) {
            // ================= WORKER =================
            BAR_ARRIVE(1 + s);                       // publish sP[s]

            // prefetch next group's x into L2 (1024 thr x 128 B = 128 KB)
            const int gn = g + gstride;
            if (gn < ngroups) {
                const char* pb = reinterpret_cast<const char*>(
                                     x + (size_t)gn * G * (WS * DDIM)) + tid * 128;
                asm volatile("prefetch.global.L2 [%0];" :: "l"(pb));
            }

            if (gprev >= 0) {
                BAR_SYNC_CTA(3 + (s ^ 1));           // DONE(s^1): pre-satisfied
                mix_store(x, out, sm + OFF_M + (s ^ 1) * 64, gprev, d0, ntok);
            }
        } else {
            // ================= ROUTER (warps 0-1) =================
            const int rwarp = warp;                  // 0 or 1
            float* sRaw = sm + OFF_RAW + s * 96;
            float* sM   = sm + OFF_M + s * 64;

            BAR_SYNC_CTA(1 + s);                     // FULL(s)

            // reduce 96 values over 32 warps: warp r takes v = 32r+lane,
            // plus v = 64+lane for the half-warp with (lane>>4)==r
            {
                const int v = 32 * rwarp + lane;
                float acc = __ldg(br + (v >> 2));
                #pragma unroll
                for (int w = 0; w < NW; w++)
                    acc += sP[w * SP_STRIDE + v];
                sRaw[v] = acc;
                if ((lane >> 4) == rwarp) {
                    const int v2 = 64 + lane;
                    float acc2 = __ldg(br + (v2 >> 2));
                    #pragma unroll
                    for (int w = 0; w < NW; w++)
                        acc2 += sP[w * SP_STRIDE + v2];
                    sRaw[v2] = acc2;
                }
            }
            BAR_SYNC_R(5);                           // both router warps see sRaw

            // scalar softmax + sinkhorn; tokens: warp r handles 2r + (lane>>4)
            {
                const int t = rwarp * 2 + (lane >> 4);

                float p0 = sRaw[0*4+t], p1 = sRaw[1*4+t], p2 = sRaw[2*4+t], p3 = sRaw[3*4+t];
                float mp = fmaxf(fmaxf(p0, p1), fmaxf(p2, p3));
                p0 = __expf(p0 - mp); p1 = __expf(p1 - mp);
                p2 = __expf(p2 - mp); p3 = __expf(p3 - mp);
                float isp = __fdividef(1.f, p0 + p1 + p2 + p3);
                p0 *= isp; p1 *= isp; p2 *= isp; p3 *= isp;

                float q0 = sRaw[4*4+t], q1 = sRaw[5*4+t], q2 = sRaw[6*4+t], q3 = sRaw[7*4+t];
                float mq = fmaxf(fmaxf(q0, q1), fmaxf(q2, q3));
                q0 = __expf(q0 - mq); q1 = __expf(q1 - mq);
                q2 = __expf(q2 - mq); q3 = __expf(q3 - mq);
                float isq = __fdividef(1.f, q0 + q1 + q2 + q3);
                q0 *= isq; q1 *= isq; q2 *= isq; q3 *= isq;

                float av[16];
                #pragma unroll
                for (int i = 0; i < 4; i++)
                    #pragma unroll
                    for (int j = 0; j < 4; j++)
                        av[i*4+j] = __expf(sRaw[(8 + i*4 + j)*4 + t] + (i == j ? 2.0f : -2.0f));

                #pragma unroll
                for (int itn = 0; itn < 4; itn++) {
                    #pragma unroll
                    for (int i = 0; i < 4; i++) {
                        float rs  = av[i*4] + av[i*4+1] + av[i*4+2] + av[i*4+3];
                        float inv = __fdividef(1.f, fmaxf(rs, EPSV));
                        av[i*4] *= inv; av[i*4+1] *= inv; av[i*4+2] *= inv; av[i*4+3] *= inv;
                    }
                    #pragma unroll
                    for (int j = 0; j < 4; j++) {
                        float cs  = av[j] + av[4+j] + av[8+j] + av[12+j];
                        float inv = __fdividef(1.f, fmaxf(cs, EPSV));
                        av[j] *= inv; av[4+j] *= inv; av[8+j] *= inv; av[12+j] *= inv;
                    }
                }

                if ((lane & 15) == 0) {
                    const float pre[4]  = {p0, p1, p2, p3};
                    const float post[4] = {q0, q1, q2, q3};
                    #pragma unroll
                    for (int i = 0; i < 4; i++) {
                        float4 mrow;
                        mrow.x = av[i*4+0] + post[i] * pre[0];
                        mrow.y = av[i*4+1] + post[i] * pre[1];
                        mrow.z = av[i*4+2] + post[i] * pre[2];
                        mrow.w = av[i*4+3] + post[i] * pre[3];
                        *reinterpret_cast<float4*>(sM + t * 16 + i * 4) = mrow;
                    }
                }
            }
            BAR_SYNC_R(6);                           // cross-router sM visibility
            BAR_ARRIVE(3 + s);                       // publish sM[s] (DONE)

            // prefetch (routers cover their share too)
            const int gn = g + gstride;
            if (gn < ngroups) {
                const char* pb = reinterpret_cast<const char*>(
                                     x + (size_t)gn * G * (WS * DDIM)) + tid * 128;
                asm volatile("prefetch.global.L2 [%0];" :: "l"(pb));
            }

            if (gprev >= 0)
                mix_store(x, out, sm + OFF_M + (s ^ 1) * 64, gprev, d0, ntok);
        }

        gprev = g;
    }

    // ---- tail: finish the last group ----
    if (gprev >= 0) {
        const int sl = (it - 1) & 1;
        if (warp >= 2) BAR_SYNC_CTA(3 + sl);         // routers arrived in-loop
        mix_store(x, out, sm + OFF_M + sl * 64, gprev, d0, ntok);
    }
}

extern "C" void kernel_launch(void* const* d_in, const int* in_sizes, int n_in,
                              void* d_out, int out_size)
{
    const float* x  = (const float*)d_in[0];
    const float* Wr = (const float*)d_in[1];
    const float* br = (const float*)d_in[2];
    float* out = (float*)d_out;

    int ntok = in_sizes[0] / (WS * DDIM);   // 8192

    cudaFuncSetAttribute(mchc_kernel,
                         cudaFuncAttributeMaxDynamicSharedMemorySize, SMEM_BYTES);

    int sms = 148, dev = 0;
    if (cudaGetDevice(&dev) == cudaSuccess) {
        int v = 0;
        if (cudaDeviceGetAttribute(&v, cudaDevAttrMultiProcessorCount, dev) == cudaSuccess && v > 0)
            sms = v;
    }
    int ngroups = (ntok + G - 1) / G;
    int grid = (ngroups < sms) ? ngroups : sms;

    mchc_kernel<<<grid, THREADS, SMEM_BYTES>>>(x, Wr, br, out, ntok);
}

// round 12
// speedup vs baseline: 1.1775x; 1.1775x over previous
#include <cuda_runtime.h>
#include <cuda_bf16.h>

// ManifoldConstrainedHyperConnection — R5 dataflow (512 thr, float4 slices,
// G=4, same-iteration mix, L2 prefetch) with de-convoyed barriers:
//   barA (id1): warps 3-15 bar.arrive (only warps 0-2 read sP), warps 0-2 sync
//   barB (id2): warps 0-1 produce M then bar.arrive; warps 2-15 bar.sync,
//               but workers issue their F-phase x loads BEFORE the sync so the
//               reduce+sinkhorn window is hidden under load latency.
// Single-slot sP/sRaw/sM (ordering via the arrive/sync chain, see analysis).

#define WRK 24
#define DDIM 2048
#define WS 4
#define THREADS 512
#define NW 16
#define G 4
#define EPSV 1e-6f

#define SMEM_WR (WRK * DDIM)            // 49152 floats (192 KB)
#define SP_STRIDE 100
#define SMEM_SP (NW * SP_STRIDE)        // 1600 floats
#define SMEM_FLOATS (SMEM_WR + SMEM_SP + 96 + 64)
#define SMEM_BYTES (SMEM_FLOATS * 4)

#define FULLM 0xffffffffu

// barriers: 1 = barA (512), 2 = barB (512), 3 = reduce-done (96), 4 = M-vis (64)
#define BAR_ARRIVE(id, n)  asm volatile("bar.arrive %0, %1;" :: "r"(id), "r"(n) : "memory")
#define BAR_SYNC(id, n)    asm volatile("bar.sync %0, %1;"   :: "r"(id), "r"(n) : "memory")

__device__ __forceinline__ float4 ld_cg4(const float* p) {
    return __ldcg(reinterpret_cast<const float4*>(p));
}

// butterfly step: values r[0..n-1] -> r[0..n/2-1]
#define BFLY_STEP(r, n, o)                                              \
    {                                                                   \
        const bool hi_ = (lane & (o)) != 0;                             \
        _Pragma("unroll")                                               \
        for (int v_ = 0; v_ < (n) / 2; v_++) {                          \
            float mine_  = hi_ ? r[v_ + (n) / 2] : r[v_];               \
            float other_ = hi_ ? r[v_] : r[v_ + (n) / 2];               \
            r[v_] = mine_ + __shfl_xor_sync(FULLM, other_, (o));        \
        }                                                               \
    }

__global__ void __launch_bounds__(THREADS, 1)
mchc_kernel(const float* __restrict__ x, const float* __restrict__ Wr,
            const float* __restrict__ br, float* __restrict__ out, int ntok)
{
    extern __shared__ float sm[];
    float* sWr  = sm;
    float* sP   = sm + SMEM_WR;
    float* sRaw = sP + SMEM_SP;      // 96 floats, raw index v = 4k + t
    float* sM   = sRaw + 96;         // 64 floats: sM[t*16 + i*4 + j]

    const int tid  = threadIdx.x;
    const int lane = tid & 31;
    const int warp = tid >> 5;
    const int d0   = tid * 4;

    // stage W_router into smem once
    for (int i = tid * 4; i < SMEM_WR; i += THREADS * 4)
        *reinterpret_cast<float4*>(sWr + i) = *reinterpret_cast<const float4*>(Wr + i);
    __syncthreads();

    const int ngroups = (ntok + G - 1) / G;

    for (int g = blockIdx.x; g < ngroups; g += gridDim.x) {
        const int n0 = g * G;

        // ---- A: pass-1 read (L2-warm from prefetch) -> stream means ----
        float4 mx[G];
        #pragma unroll
        for (int t = 0; t < G; t++) {
            mx[t] = make_float4(0.f, 0.f, 0.f, 0.f);
            if (n0 + t < ntok) {
                const float* p = x + (size_t)(n0 + t) * (WS * DDIM) + d0;
                #pragma unroll
                for (int w = 0; w < WS; w++) {
                    float4 v = ld_cg4(p + w * DDIM);
                    mx[t].x += v.x; mx[t].y += v.y; mx[t].z += v.z; mx[t].w += v.w;
                }
                mx[t].x *= 0.25f; mx[t].y *= 0.25f; mx[t].z *= 0.25f; mx[t].w *= 0.25f;
            }
        }

        // ---- B: router partials, 3 sets of 32 values (v = 4k + t) ----
        float res0, res1, res2;
        #pragma unroll
        for (int set = 0; set < 3; set++) {
            float a[32];
            #pragma unroll
            for (int kk = 0; kk < 8; kk++) {
                const int k = 8 * set + kk;
                float4 wv = *reinterpret_cast<const float4*>(sWr + k * DDIM + d0);
                #pragma unroll
                for (int t = 0; t < G; t++)
                    a[kk * 4 + t] = wv.x * mx[t].x + wv.y * mx[t].y +
                                    wv.z * mx[t].z + wv.w * mx[t].w;
            }
            BFLY_STEP(a, 32, 16)
            BFLY_STEP(a, 16, 8)
            BFLY_STEP(a, 8, 4)
            BFLY_STEP(a, 4, 2)
            BFLY_STEP(a, 2, 1)
            if (set == 0) res0 = a[0];
            else if (set == 1) res1 = a[0];
            else res2 = a[0];
        }
        sP[warp * SP_STRIDE + lane]      = res0;
        sP[warp * SP_STRIDE + 32 + lane] = res1;
        sP[warp * SP_STRIDE + 64 + lane] = res2;

        if (warp >= 3) {
            // ============ WORKER (warps 3-15): never blocks at barA ============
            BAR_ARRIVE(1, THREADS);                 // publish sP

            // warm next group's x into L2
            const int gn = g + gridDim.x;
            if (gn < ngroups) {
                const char* pb = reinterpret_cast<const char*>(
                                     x + (size_t)gn * G * (WS * DDIM)) + tid * 256;
                asm volatile("prefetch.global.L2 [%0];" :: "l"(pb));
                asm volatile("prefetch.global.L2 [%0];" :: "l"(pb + 128));
            }

            // F-phase loads issued BEFORE waiting on M (independent of M)
            float4 xf[G][WS];
            #pragma unroll
            for (int t = 0; t < G; t++) {
                const float* p = x + (size_t)(n0 + t) * (WS * DDIM) + d0;
                const bool ok = (n0 + t) < ntok;
                #pragma unroll
                for (int w = 0; w < WS; w++)
                    xf[t][w] = ok ? ld_cg4(p + w * DDIM) : make_float4(0,0,0,0);
            }

            BAR_SYNC(2, THREADS);                   // wait for M (hidden by loads)

            #pragma unroll
            for (int t = 0; t < G; t++) {
                if (n0 + t < ntok) {
                    float* o = out + (size_t)(n0 + t) * (WS * DDIM) + d0;
                    #pragma unroll
                    for (int i = 0; i < WS; i++) {
                        float4 Mi = *reinterpret_cast<const float4*>(sM + t * 16 + i * 4);
                        float4 ov;
                        ov.x = Mi.x*xf[t][0].x + Mi.y*xf[t][1].x + Mi.z*xf[t][2].x + Mi.w*xf[t][3].x;
                        ov.y = Mi.x*xf[t][0].y + Mi.y*xf[t][1].y + Mi.z*xf[t][2].y + Mi.w*xf[t][3].y;
                        ov.z = Mi.x*xf[t][0].z + Mi.y*xf[t][1].z + Mi.z*xf[t][2].z + Mi.w*xf[t][3].z;
                        ov.w = Mi.x*xf[t][0].w + Mi.y*xf[t][1].w + Mi.z*xf[t][2].w + Mi.w*xf[t][3].w;
                        __stcs(reinterpret_cast<float4*>(o + i * DDIM), ov);
                    }
                }
            }
        } else {
            // ============ ROUTER (warps 0-2) ============
            BAR_SYNC(1, THREADS);                   // barA: sP complete

            // reduce: warp w owns values v = 32w + lane (v = 4k + t)
            {
                float acc = __ldg(br + 8 * warp + (lane >> 2));
                #pragma unroll
                for (int w = 0; w < NW; w++)
                    acc += sP[w * SP_STRIDE + 32 * warp + lane];
                sRaw[32 * warp + lane] = acc;
            }
            BAR_SYNC(3, 96);                        // warps 0-2: sRaw complete

            if (warp < 2) {
                const int t = warp * 2 + (lane >> 4);   // token 0..3

                float p0 = sRaw[0*4+t], p1 = sRaw[1*4+t], p2 = sRaw[2*4+t], p3 = sRaw[3*4+t];
                float mp = fmaxf(fmaxf(p0, p1), fmaxf(p2, p3));
                p0 = __expf(p0 - mp); p1 = __expf(p1 - mp);
                p2 = __expf(p2 - mp); p3 = __expf(p3 - mp);
                float isp = __fdividef(1.f, p0 + p1 + p2 + p3);
                p0 *= isp; p1 *= isp; p2 *= isp; p3 *= isp;

                float q0 = sRaw[4*4+t], q1 = sRaw[5*4+t], q2 = sRaw[6*4+t], q3 = sRaw[7*4+t];
                float mq = fmaxf(fmaxf(q0, q1), fmaxf(q2, q3));
                q0 = __expf(q0 - mq); q1 = __expf(q1 - mq);
                q2 = __expf(q2 - mq); q3 = __expf(q3 - mq);
                float isq = __fdividef(1.f, q0 + q1 + q2 + q3);
                q0 *= isq; q1 *= isq; q2 *= isq; q3 *= isq;

                float av[16];
                #pragma unroll
                for (int i = 0; i < 4; i++)
                    #pragma unroll
                    for (int j = 0; j < 4; j++)
                        av[i*4+j] = __expf(sRaw[(8 + i*4 + j)*4 + t] + (i == j ? 2.0f : -2.0f));

                #pragma unroll
                for (int it = 0; it < 4; it++) {
                    #pragma unroll
                    for (int i = 0; i < 4; i++) {
                        float rs  = av[i*4] + av[i*4+1] + av[i*4+2] + av[i*4+3];
                        float inv = __fdividef(1.f, fmaxf(rs, EPSV));
                        av[i*4] *= inv; av[i*4+1] *= inv; av[i*4+2] *= inv; av[i*4+3] *= inv;
                    }
                    #pragma unroll
                    for (int j = 0; j < 4; j++) {
                        float cs  = av[j] + av[4+j] + av[8+j] + av[12+j];
                        float inv = __fdividef(1.f, fmaxf(cs, EPSV));
                        av[j] *= inv; av[4+j] *= inv; av[8+j] *= inv; av[12+j] *= inv;
                    }
                }

                if ((lane & 15) == 0) {
                    const float pre[4]  = {p0, p1, p2, p3};
                    const float post[4] = {q0, q1, q2, q3};
                    #pragma unroll
                    for (int i = 0; i < 4; i++) {
                        float4 mrow;
                        mrow.x = av[i*4+0] + post[i] * pre[0];
                        mrow.y = av[i*4+1] + post[i] * pre[1];
                        mrow.z = av[i*4+2] + post[i] * pre[2];
                        mrow.w = av[i*4+3] + post[i] * pre[3];
                        *reinterpret_cast<float4*>(sM + t * 16 + i * 4) = mrow;
                    }
                }
                BAR_SYNC(4, 64);                    // warps 0-1: full sM visible
                BAR_ARRIVE(2, THREADS);             // release barB
            } else {
                BAR_SYNC(2, THREADS);               // warp 2 waits for M
            }

            // prefetch share for warps 0-2
            const int gn = g + gridDim.x;
            if (gn < ngroups) {
                const char* pb = reinterpret_cast<const char*>(
                                     x + (size_t)gn * G * (WS * DDIM)) + tid * 256;
                asm volatile("prefetch.global.L2 [%0];" :: "l"(pb));
                asm volatile("prefetch.global.L2 [%0];" :: "l"(pb + 128));
            }

            // F for warps 0-2 (loads after M; 3 of 16 warps, minor)
            #pragma unroll
            for (int t = 0; t < G; t++) {
                if (n0 + t < ntok) {
                    const float* p = x + (size_t)(n0 + t) * (WS * DDIM) + d0;
                    float*       o = out + (size_t)(n0 + t) * (WS * DDIM) + d0;
                    float4 x0 = ld_cg4(p);
                    float4 x1 = ld_cg4(p + DDIM);
                    float4 x2 = ld_cg4(p + 2 * DDIM);
                    float4 x3 = ld_cg4(p + 3 * DDIM);
                    #pragma unroll
                    for (int i = 0; i < WS; i++) {
                        float4 Mi = *reinterpret_cast<const float4*>(sM + t * 16 + i * 4);
                        float4 ov;
                        ov.x = Mi.x*x0.x + Mi.y*x1.x + Mi.z*x2.x + Mi.w*x3.x;
                        ov.y = Mi.x*x0.y + Mi.y*x1.y + Mi.z*x2.y + Mi.w*x3.y;
                        ov.z = Mi.x*x0.z + Mi.y*x1.z + Mi.z*x2.z + Mi.w*x3.z;
                        ov.w = Mi.x*x0.w + Mi.y*x1.w + Mi.z*x2.w + Mi.w*x3.w;
                        __stcs(reinterpret_cast<float4*>(o + i * DDIM), ov);
                    }
                }
            }
        }
        // slot reuse ordering: sP(it+1) writes happen only after this thread
        // passed barB(it) (workers) or read sP (routers, before their arrive);
        // sM(it+1) is written by warps 0-1 only after barA(it+1), which
        // requires every worker to have finished F(it) (program order).
    }
}

extern "C" void kernel_launch(void* const* d_in, const int* in_sizes, int n_in,
                              void* d_out, int out_size)
{
    const float* x  = (const float*)d_in[0];
    const float* Wr = (const float*)d_in[1];
    const float* br = (const float*)d_in[2];
    float* out = (float*)d_out;

    int ntok = in_sizes[0] / (WS * DDIM);   // 8192

    cudaFuncSetAttribute(mchc_kernel,
                         cudaFuncAttributeMaxDynamicSharedMemorySize, SMEM_BYTES);

    int sms = 148, dev = 0;
    if (cudaGetDevice(&dev) == cudaSuccess) {
        int v = 0;
        if (cudaDeviceGetAttribute(&v, cudaDevAttrMultiProcessorCount, dev) == cudaSuccess && v > 0)
            sms = v;
    }
    int ngroups = (ntok + G - 1) / G;
    int grid = (ngroups < sms) ? ngroups : sms;

    mchc_kernel<<<grid, THREADS, SMEM_BYTES>>>(x, Wr, br, out, ntok);
}